// round 2
// baseline (speedup 1.0000x reference)
#include <cuda_runtime.h>
#include <math.h>

#define N_NODES 10000
#define N_EDGES 160000
#define ETOT (N_EDGES + N_NODES)   /* 170000 with self loops */
#define F_IN 768
#define H1 4
#define CDIM 128
#define HC1 (H1 * CDIM)            /* 512 */
#define NG 16
#define NOUT 10

// ---------------- scratch (device globals; no runtime allocation) -------------
__device__ float g_h1  [N_NODES * HC1];
__device__ float g_out1[N_NODES * HC1];
__device__ float g_als1[N_NODES * H1];
__device__ float g_ald1[N_NODES * H1];
__device__ float g_m1  [N_NODES * H1];
__device__ float g_den1[N_NODES * H1];
__device__ float g_e1  [ETOT * H1];

__device__ float g_h2  [N_NODES * CDIM];
__device__ float g_out2[N_NODES * CDIM];
__device__ float g_als2[N_NODES];
__device__ float g_ald2[N_NODES];
__device__ float g_m2  [N_NODES];
__device__ float g_den2[N_NODES];
__device__ float g_e2  [ETOT];

__device__ float g_pool[NG * CDIM];
__device__ float g_cnt [NG];

// ---------------- utility kernels --------------------------------------------
__global__ void fill_kernel(float* p, float v, int n) {
    int i = blockIdx.x * blockDim.x + threadIdx.x;
    if (i < n) p[i] = v;
}

__device__ __forceinline__ void atomicMaxFloat(float* addr, float val) {
    int old = __float_as_int(*addr);
    while (__int_as_float(old) < val) {
        int assumed = old;
        old = atomicCAS((int*)addr, assumed, __float_as_int(val));
        if (old == assumed) break;
    }
}

// ---------------- fp32 tiled GEMM: C[M,N] = A[M,K] @ B[K,N] ------------------
// BM=128 BN=128 BK=8, 256 threads, 8x8 per thread. N,K multiples of 8; M guarded.
__global__ __launch_bounds__(256, 2)
void gemm_f32(const float* __restrict__ A, const float* __restrict__ B,
              float* __restrict__ Cm, int M, int N, int K) {
    __shared__ float As[8][128];
    __shared__ float Bs[8][128];
    const int tid  = threadIdx.x;
    const int row0 = blockIdx.y * 128;
    const int col0 = blockIdx.x * 128;
    const int tr = (tid >> 4) << 3;   // 0..120
    const int tc = (tid & 15) << 3;   // 0..120

    float acc[8][8];
#pragma unroll
    for (int i = 0; i < 8; i++)
#pragma unroll
        for (int j = 0; j < 8; j++) acc[i][j] = 0.f;

    const int ar  = tid >> 1;          // 0..127
    const int ac4 = (tid & 1) << 2;    // 0 or 4
    const int br  = tid >> 5;          // 0..7
    const int bn4 = (tid & 31) << 2;   // 0..124

    for (int k0 = 0; k0 < K; k0 += 8) {
        float4 av = make_float4(0.f, 0.f, 0.f, 0.f);
        int arow = row0 + ar;
        if (arow < M) av = *(const float4*)&A[(size_t)arow * K + k0 + ac4];
        As[ac4 + 0][ar] = av.x;
        As[ac4 + 1][ar] = av.y;
        As[ac4 + 2][ar] = av.z;
        As[ac4 + 3][ar] = av.w;
        float4 bv = *(const float4*)&B[(size_t)(k0 + br) * N + col0 + bn4];
        *(float4*)&Bs[br][bn4] = bv;
        __syncthreads();
#pragma unroll
        for (int kk = 0; kk < 8; kk++) {
            float a[8], b[8];
#pragma unroll
            for (int i = 0; i < 8; i++) a[i] = As[kk][tr + i];
#pragma unroll
            for (int j = 0; j < 8; j++) b[j] = Bs[kk][tc + j];
#pragma unroll
            for (int i = 0; i < 8; i++)
#pragma unroll
                for (int j = 0; j < 8; j++) acc[i][j] = fmaf(a[i], b[j], acc[i][j]);
        }
        __syncthreads();
    }
#pragma unroll
    for (int i = 0; i < 8; i++) {
        int row = row0 + tr + i;
        if (row < M) {
#pragma unroll
            for (int j = 0; j < 8; j += 4) {
                float4 v = make_float4(acc[i][j], acc[i][j+1], acc[i][j+2], acc[i][j+3]);
                *(float4*)&Cm[(size_t)row * N + col0 + tc + j] = v;
            }
        }
    }
}

// ---------------- attention logits: one warp per (node, head) ----------------
// blockDim = 32*H, grid = N
__global__ void att_logits(const float* __restrict__ feat,
                           const float* __restrict__ asrc,
                           const float* __restrict__ adst,
                           float* __restrict__ osrc, float* __restrict__ odst,
                           int H) {
    int n    = blockIdx.x;
    int h    = threadIdx.x >> 5;
    int lane = threadIdx.x & 31;
    const float* f = feat + ((size_t)n * H + h) * CDIM;
    float ss = 0.f, sd = 0.f;
#pragma unroll
    for (int c = lane; c < CDIM; c += 32) {
        float v = f[c];
        ss = fmaf(v, asrc[h * CDIM + c], ss);
        sd = fmaf(v, adst[h * CDIM + c], sd);
    }
#pragma unroll
    for (int o = 16; o; o >>= 1) {
        ss += __shfl_down_sync(0xffffffffu, ss, o);
        sd += __shfl_down_sync(0xffffffffu, sd, o);
    }
    if (lane == 0) { osrc[n * H + h] = ss; odst[n * H + h] = sd; }
}

// ---------------- per-(edge,head): leaky-relu logit + segment max ------------
__global__ void edge_logit_max(const int* __restrict__ ei,
                               const float* __restrict__ als,
                               const float* __restrict__ ald,
                               float* __restrict__ e_out, float* __restrict__ m,
                               int H) {
    int gi = blockIdx.x * blockDim.x + threadIdx.x;
    int idx = gi / H, h = gi - idx * H;
    if (idx >= ETOT) return;
    int s, d;
    if (idx < N_EDGES) { s = ei[idx]; d = ei[N_EDGES + idx]; }
    else               { s = d = idx - N_EDGES; }
    float v = als[s * H + h] + ald[d * H + h];
    v = v > 0.f ? v : 0.2f * v;
    e_out[(size_t)idx * H + h] = v;
    atomicMaxFloat(&m[d * H + h], v);
}

// ---------------- per-(edge,head): exp + segment sum (stores exp in-place) ---
__global__ void edge_exp_den(const int* __restrict__ ei,
                             float* __restrict__ e_buf,
                             const float* __restrict__ m,
                             float* __restrict__ den, int H) {
    int gi = blockIdx.x * blockDim.x + threadIdx.x;
    int idx = gi / H, h = gi - idx * H;
    if (idx >= ETOT) return;
    int d;
    if (idx < N_EDGES) d = ei[N_EDGES + idx]; else d = idx - N_EDGES;
    float ex = __expf(e_buf[(size_t)idx * H + h] - m[d * H + h]);
    e_buf[(size_t)idx * H + h] = ex;
    atomicAdd(&den[d * H + h], ex);
}

// ---------------- weighted scatter-aggregate: warp per (edge, head) ----------
__global__ void aggregate(const int* __restrict__ ei,
                          const float* __restrict__ feat,
                          const float* __restrict__ e_ex,
                          const float* __restrict__ den,
                          float* __restrict__ out, int H) {
    int gw   = (blockIdx.x * blockDim.x + threadIdx.x) >> 5;
    int lane = threadIdx.x & 31;
    int idx = gw / H, h = gw - idx * H;
    if (idx >= ETOT) return;
    int s, d;
    if (idx < N_EDGES) { s = ei[idx]; d = ei[N_EDGES + idx]; }
    else               { s = d = idx - N_EDGES; }
    float alpha = e_ex[(size_t)idx * H + h] / (den[d * H + h] + 1e-16f);
    const float4* fs = (const float4*)(feat + ((size_t)s * H + h) * CDIM);
    float4 v = fs[lane];
    float* o = out + ((size_t)d * H + h) * CDIM + lane * 4;
    atomicAdd(o + 0, alpha * v.x);
    atomicAdd(o + 1, alpha * v.y);
    atomicAdd(o + 2, alpha * v.z);
    atomicAdd(o + 3, alpha * v.w);
}

// ---------------- bias + relu -------------------------------------------------
__global__ void bias_relu(float* __restrict__ p, const float* __restrict__ b,
                          int n, int stride) {
    int i = blockIdx.x * blockDim.x + threadIdx.x;
    if (i >= n) return;
    float v = p[i] + b[i % stride];
    p[i] = v > 0.f ? v : 0.f;
}

// ---------------- pooling -----------------------------------------------------
__global__ void pool_sum(const float* __restrict__ feat,
                         const int* __restrict__ batch,
                         float* __restrict__ pool) {
    int i = blockIdx.x * blockDim.x + threadIdx.x;
    if (i >= N_NODES * CDIM) return;
    int n = i / CDIM, c = i - n * CDIM;
    atomicAdd(&pool[batch[n] * CDIM + c], feat[i]);
}

__global__ void pool_cnt(const int* __restrict__ batch, float* __restrict__ cnt) {
    int n = blockIdx.x * blockDim.x + threadIdx.x;
    if (n >= N_NODES) return;
    atomicAdd(&cnt[batch[n]], 1.0f);
}

// ---------------- classifier: out[g*10+o] -------------------------------------
__global__ void classifier(const float* __restrict__ pool, const float* __restrict__ cnt,
                           const float* __restrict__ Wc, const float* __restrict__ bc,
                           float* __restrict__ out) {
    int t = threadIdx.x;
    if (t >= NG * NOUT) return;
    int g = t / NOUT, o = t - g * NOUT;
    float inv = 1.0f / fmaxf(cnt[g], 1.0f);
    float sum = bc[o];
    for (int k = 0; k < CDIM; k++)
        sum = fmaf(pool[g * CDIM + k] * inv, Wc[k * NOUT + o], sum);
    out[t] = sum;
}

// ---------------- host orchestration ------------------------------------------
static inline int ceil_div(int a, int b) { return (a + b - 1) / b; }

extern "C" void kernel_launch(void* const* d_in, const int* in_sizes, int n_in,
                              void* d_out, int out_size) {
    const float* x      = (const float*)d_in[0];
    const int*   ei     = (const int*)d_in[1];
    const int*   batch  = (const int*)d_in[2];
    const float* W1     = (const float*)d_in[3];
    const float* asrc1  = (const float*)d_in[4];
    const float* adst1  = (const float*)d_in[5];
    const float* b1     = (const float*)d_in[6];
    const float* W2     = (const float*)d_in[7];
    const float* asrc2  = (const float*)d_in[8];
    const float* adst2  = (const float*)d_in[9];
    const float* b2     = (const float*)d_in[10];
    const float* Wc     = (const float*)d_in[11];
    const float* bc     = (const float*)d_in[12];
    float*       out    = (float*)d_out;

    float *h1, *out1, *als1, *ald1, *m1, *den1, *e1;
    float *h2, *out2, *als2, *ald2, *m2, *den2, *e2;
    float *pool, *cnt;
    cudaGetSymbolAddress((void**)&h1,   g_h1);
    cudaGetSymbolAddress((void**)&out1, g_out1);
    cudaGetSymbolAddress((void**)&als1, g_als1);
    cudaGetSymbolAddress((void**)&ald1, g_ald1);
    cudaGetSymbolAddress((void**)&m1,   g_m1);
    cudaGetSymbolAddress((void**)&den1, g_den1);
    cudaGetSymbolAddress((void**)&e1,   g_e1);
    cudaGetSymbolAddress((void**)&h2,   g_h2);
    cudaGetSymbolAddress((void**)&out2, g_out2);
    cudaGetSymbolAddress((void**)&als2, g_als2);
    cudaGetSymbolAddress((void**)&ald2, g_ald2);
    cudaGetSymbolAddress((void**)&m2,   g_m2);
    cudaGetSymbolAddress((void**)&den2, g_den2);
    cudaGetSymbolAddress((void**)&e2,   g_e2);
    cudaGetSymbolAddress((void**)&pool, g_pool);
    cudaGetSymbolAddress((void**)&cnt,  g_cnt);

    const int TB = 256;

    // --- init scratch ---
    fill_kernel<<<ceil_div(N_NODES * HC1, TB), TB>>>(out1, 0.f, N_NODES * HC1);
    fill_kernel<<<ceil_div(N_NODES * H1, TB), TB>>>(m1, -INFINITY, N_NODES * H1);
    fill_kernel<<<ceil_div(N_NODES * H1, TB), TB>>>(den1, 0.f, N_NODES * H1);
    fill_kernel<<<ceil_div(N_NODES * CDIM, TB), TB>>>(out2, 0.f, N_NODES * CDIM);
    fill_kernel<<<ceil_div(N_NODES, TB), TB>>>(m2, -INFINITY, N_NODES);
    fill_kernel<<<ceil_div(N_NODES, TB), TB>>>(den2, 0.f, N_NODES);
    fill_kernel<<<ceil_div(NG * CDIM, TB), TB>>>(pool, 0.f, NG * CDIM);
    fill_kernel<<<1, 32>>>(cnt, 0.f, NG);

    // --- layer 1 ---
    gemm_f32<<<dim3(HC1 / 128, ceil_div(N_NODES, 128)), 256>>>(x, W1, h1, N_NODES, HC1, F_IN);
    att_logits<<<N_NODES, 32 * H1>>>(h1, asrc1, adst1, als1, ald1, H1);
    edge_logit_max<<<ceil_div(ETOT * H1, TB), TB>>>(ei, als1, ald1, e1, m1, H1);
    edge_exp_den<<<ceil_div(ETOT * H1, TB), TB>>>(ei, e1, m1, den1, H1);
    aggregate<<<ceil_div(ETOT * H1 * 32, TB), TB>>>(ei, h1, e1, den1, out1, H1);
    bias_relu<<<ceil_div(N_NODES * HC1, TB), TB>>>(out1, b1, N_NODES * HC1, HC1);

    // --- layer 2 ---
    gemm_f32<<<dim3(CDIM / 128, ceil_div(N_NODES, 128)), 256>>>(out1, W2, h2, N_NODES, CDIM, HC1);
    att_logits<<<N_NODES, 32>>>(h2, asrc2, adst2, als2, ald2, 1);
    edge_logit_max<<<ceil_div(ETOT, TB), TB>>>(ei, als2, ald2, e2, m2, 1);
    edge_exp_den<<<ceil_div(ETOT, TB), TB>>>(ei, e2, m2, den2, 1);
    aggregate<<<ceil_div(ETOT * 32, TB), TB>>>(ei, h2, e2, den2, out2, 1);
    bias_relu<<<ceil_div(N_NODES * CDIM, TB), TB>>>(out2, b2, N_NODES * CDIM, CDIM);

    // --- pool + classify ---
    pool_sum<<<ceil_div(N_NODES * CDIM, TB), TB>>>(out2, batch, pool);
    pool_cnt<<<ceil_div(N_NODES, TB), TB>>>(batch, cnt);
    classifier<<<1, NG * NOUT>>>(pool, cnt, Wc, bc, out);
}

// round 3
// speedup vs baseline: 1.6650x; 1.6650x over previous
#include <cuda_runtime.h>
#include <math.h>

#define N_NODES 10000
#define N_EDGES 160000
#define ETOT (N_EDGES + N_NODES)   /* 170000 with self loops */
#define F_IN 768
#define H1 4
#define CDIM 128
#define HC1 (H1 * CDIM)            /* 512 */
#define NG 16
#define NOUT 10

// ---------------- scratch (device globals; no runtime allocation) -------------
// zero-initialized region (packed so a single fill covers everything)
#define Z_OUT1 0
#define Z_DEN1 (Z_OUT1 + N_NODES * HC1)
#define Z_OUT2 (Z_DEN1 + N_NODES * H1)
#define Z_DEN2 (Z_OUT2 + N_NODES * CDIM)
#define Z_POOL (Z_DEN2 + N_NODES)
#define Z_CNT  (Z_POOL + NG * CDIM)
#define ZTOT   (Z_CNT + NG)
__device__ float g_zero[ZTOT];

#define MI_M1 0
#define MI_M2 (MI_M1 + N_NODES * H1)
#define MITOT (MI_M2 + N_NODES)
__device__ float g_minf[MITOT];

__device__ float g_h1  [N_NODES * HC1];
__device__ float g_als1[N_NODES * H1];
__device__ float g_ald1[N_NODES * H1];
__device__ float g_e1  [ETOT * H1];

__device__ float g_h2  [N_NODES * CDIM];
__device__ float g_als2[N_NODES];
__device__ float g_ald2[N_NODES];
__device__ float g_e2  [ETOT];

// ---------------- utility kernels --------------------------------------------
__global__ void fill4_kernel(float4* p, float v, int n4) {
    int i = blockIdx.x * blockDim.x + threadIdx.x;
    if (i < n4) p[i] = make_float4(v, v, v, v);
}
__global__ void fill_kernel(float* p, float v, int n) {
    int i = blockIdx.x * blockDim.x + threadIdx.x;
    if (i < n) p[i] = v;
}

__device__ __forceinline__ void atomicMaxFloat(float* addr, float val) {
    int old = __float_as_int(*addr);
    while (__int_as_float(old) < val) {
        int assumed = old;
        old = atomicCAS((int*)addr, assumed, __float_as_int(val));
        if (old == assumed) break;
    }
}

// ---------------- TF32 tensor-core GEMM: C[M,N] = A[M,K] @ B[K,N] ------------
// BM=128, BN=128, BK=16, 256 threads (8 warps: 2 along M x 4 along N),
// warp tile 64x32 via m16n8k8 tf32 mma. cp.async double buffering.
// Requires: K % 16 == 0, N % 128 == 0. M guarded.
#define BK 16
#define A_PAD 20   /* As stride in floats: conflict-free fragment loads */
#define B_PAD 136  /* Bs stride in floats: conflict-free fragment loads */

__device__ __forceinline__ unsigned cvta_s(const void* p) {
    return (unsigned)__cvta_generic_to_shared(p);
}
__device__ __forceinline__ void cp_async16(unsigned s, const void* g) {
    asm volatile("cp.async.ca.shared.global [%0], [%1], 16;\n" :: "r"(s), "l"(g));
}
__device__ __forceinline__ void cp_commit() { asm volatile("cp.async.commit_group;\n"); }
__device__ __forceinline__ void cp_wait1() { asm volatile("cp.async.wait_group 1;\n"); }
__device__ __forceinline__ void cp_wait0() { asm volatile("cp.async.wait_group 0;\n"); }
__device__ __forceinline__ unsigned f2tf32(float f) {
    unsigned u;
    asm("cvt.rna.tf32.f32 %0, %1;\n" : "=r"(u) : "f"(f));
    return u;
}

__global__ __launch_bounds__(256)
void gemm_tf32(const float* __restrict__ A, const float* __restrict__ B,
               float* __restrict__ Cm, int M, int N, int K) {
    __shared__ float As[2][128 * A_PAD];
    __shared__ float Bs[2][BK * B_PAD];

    const int tid  = threadIdx.x;
    const int lane = tid & 31;
    const int warp = tid >> 5;
    const int wm = warp & 1;          // 0..1
    const int wn = warp >> 1;         // 0..3
    const int m_base = wm * 64;
    const int n_base = wn * 32;
    const int g = lane >> 2;          // 0..7
    const int t = lane & 3;           // 0..3
    const int row0 = blockIdx.y * 128;
    const int col0 = blockIdx.x * 128;

    float acc[4][4][4];
#pragma unroll
    for (int i = 0; i < 4; i++)
#pragma unroll
        for (int j = 0; j < 4; j++)
#pragma unroll
            for (int r = 0; r < 4; r++) acc[i][j][r] = 0.f;

    // load maps (2 chunks each for A and B per thread)
    // A: 512 chunks = 128 rows x 4 chunks of 4 floats
    // B: 512 chunks = 16 rows x 32 chunks of 4 floats
    const int a_row0c = tid >> 2, a_c = (tid & 3);          // chunk ids tid, tid+256
    const int b_k0c   = tid >> 5, b_n = (tid & 31);

    const int KT = K / BK;

    auto load_tile = [&](int kt, int buf) {
        const int k0 = kt * BK;
        // A chunks
#pragma unroll
        for (int h = 0; h < 2; h++) {
            int row = a_row0c + h * 64;
            int grow = row0 + row;
            if (grow >= M) grow = M - 1;  // clamp: dead rows never stored
            unsigned s = cvta_s(&As[buf][row * A_PAD + a_c * 4]);
            cp_async16(s, &A[(size_t)grow * K + k0 + a_c * 4]);
        }
        // B chunks
#pragma unroll
        for (int h = 0; h < 2; h++) {
            int k = b_k0c + h * 8;
            unsigned s = cvta_s(&Bs[buf][k * B_PAD + b_n * 4]);
            cp_async16(s, &B[(size_t)(k0 + k) * N + col0 + b_n * 4]);
        }
        cp_commit();
    };

    load_tile(0, 0);

    for (int kt = 0; kt < KT; kt++) {
        const int buf = kt & 1;
        if (kt + 1 < KT) { load_tile(kt + 1, buf ^ 1); cp_wait1(); }
        else             { cp_wait0(); }
        __syncthreads();

#pragma unroll
        for (int kk = 0; kk < 2; kk++) {
            const int ks = kk * 8;
            unsigned a[4][4];
#pragma unroll
            for (int mf = 0; mf < 4; mf++) {
                const int r = m_base + mf * 16;
                a[mf][0] = f2tf32(As[buf][(r + g)     * A_PAD + ks + t]);
                a[mf][1] = f2tf32(As[buf][(r + g + 8) * A_PAD + ks + t]);
                a[mf][2] = f2tf32(As[buf][(r + g)     * A_PAD + ks + t + 4]);
                a[mf][3] = f2tf32(As[buf][(r + g + 8) * A_PAD + ks + t + 4]);
            }
            unsigned b[4][2];
#pragma unroll
            for (int nf = 0; nf < 4; nf++) {
                const int c = n_base + nf * 8 + g;
                b[nf][0] = f2tf32(Bs[buf][(ks + t)     * B_PAD + c]);
                b[nf][1] = f2tf32(Bs[buf][(ks + t + 4) * B_PAD + c]);
            }
#pragma unroll
            for (int mf = 0; mf < 4; mf++)
#pragma unroll
                for (int nf = 0; nf < 4; nf++) {
                    asm volatile(
                        "mma.sync.aligned.m16n8k8.row.col.f32.tf32.tf32.f32 "
                        "{%0,%1,%2,%3}, {%4,%5,%6,%7}, {%8,%9}, {%0,%1,%2,%3};\n"
                        : "+f"(acc[mf][nf][0]), "+f"(acc[mf][nf][1]),
                          "+f"(acc[mf][nf][2]), "+f"(acc[mf][nf][3])
                        : "r"(a[mf][0]), "r"(a[mf][1]), "r"(a[mf][2]), "r"(a[mf][3]),
                          "r"(b[nf][0]), "r"(b[nf][1]));
                }
        }
        __syncthreads();
    }

    // epilogue
#pragma unroll
    for (int mf = 0; mf < 4; mf++) {
        const int r0 = row0 + m_base + mf * 16 + g;
        const int r1 = r0 + 8;
#pragma unroll
        for (int nf = 0; nf < 4; nf++) {
            const int c = col0 + n_base + nf * 8 + t * 2;
            if (r0 < M)
                *(float2*)&Cm[(size_t)r0 * N + c] = make_float2(acc[mf][nf][0], acc[mf][nf][1]);
            if (r1 < M)
                *(float2*)&Cm[(size_t)r1 * N + c] = make_float2(acc[mf][nf][2], acc[mf][nf][3]);
        }
    }
}

// ---------------- attention logits: one warp per (node, head) ----------------
__global__ void att_logits(const float* __restrict__ feat,
                           const float* __restrict__ asrc,
                           const float* __restrict__ adst,
                           float* __restrict__ osrc, float* __restrict__ odst,
                           int H) {
    int n    = blockIdx.x;
    int h    = threadIdx.x >> 5;
    int lane = threadIdx.x & 31;
    const float* f = feat + ((size_t)n * H + h) * CDIM;
    float ss = 0.f, sd = 0.f;
#pragma unroll
    for (int c = lane; c < CDIM; c += 32) {
        float v = f[c];
        ss = fmaf(v, asrc[h * CDIM + c], ss);
        sd = fmaf(v, adst[h * CDIM + c], sd);
    }
#pragma unroll
    for (int o = 16; o; o >>= 1) {
        ss += __shfl_down_sync(0xffffffffu, ss, o);
        sd += __shfl_down_sync(0xffffffffu, sd, o);
    }
    if (lane == 0) { osrc[n * H + h] = ss; odst[n * H + h] = sd; }
}

// ---------------- per-(edge,head): leaky-relu logit + segment max ------------
__global__ void edge_logit_max(const int* __restrict__ ei,
                               const float* __restrict__ als,
                               const float* __restrict__ ald,
                               float* __restrict__ e_out, float* __restrict__ m,
                               int H) {
    int gi = blockIdx.x * blockDim.x + threadIdx.x;
    int idx = gi / H, h = gi - idx * H;
    if (idx >= ETOT) return;
    int s, d;
    if (idx < N_EDGES) { s = ei[idx]; d = ei[N_EDGES + idx]; }
    else               { s = d = idx - N_EDGES; }
    float v = als[s * H + h] + ald[d * H + h];
    v = v > 0.f ? v : 0.2f * v;
    e_out[(size_t)idx * H + h] = v;
    atomicMaxFloat(&m[d * H + h], v);
}

// ---------------- per-(edge,head): exp + segment sum (stores exp in-place) ---
__global__ void edge_exp_den(const int* __restrict__ ei,
                             float* __restrict__ e_buf,
                             const float* __restrict__ m,
                             float* __restrict__ den, int H) {
    int gi = blockIdx.x * blockDim.x + threadIdx.x;
    int idx = gi / H, h = gi - idx * H;
    if (idx >= ETOT) return;
    int d;
    if (idx < N_EDGES) d = ei[N_EDGES + idx]; else d = idx - N_EDGES;
    float ex = __expf(e_buf[(size_t)idx * H + h] - m[d * H + h]);
    e_buf[(size_t)idx * H + h] = ex;
    atomicAdd(&den[d * H + h], ex);
}

// ---------------- weighted scatter-aggregate: warp per (edge, head) ----------
__global__ void aggregate(const int* __restrict__ ei,
                          const float* __restrict__ feat,
                          const float* __restrict__ e_ex,
                          const float* __restrict__ den,
                          float* __restrict__ out, int H) {
    int gw   = (blockIdx.x * blockDim.x + threadIdx.x) >> 5;
    int lane = threadIdx.x & 31;
    int idx = gw / H, h = gw - idx * H;
    if (idx >= ETOT) return;
    int s, d;
    if (idx < N_EDGES) { s = ei[idx]; d = ei[N_EDGES + idx]; }
    else               { s = d = idx - N_EDGES; }
    float alpha = e_ex[(size_t)idx * H + h] / (den[d * H + h] + 1e-16f);
    const float4* fs = (const float4*)(feat + ((size_t)s * H + h) * CDIM);
    float4 v = fs[lane];
    float* o = out + ((size_t)d * H + h) * CDIM + lane * 4;
    atomicAdd(o + 0, alpha * v.x);
    atomicAdd(o + 1, alpha * v.y);
    atomicAdd(o + 2, alpha * v.z);
    atomicAdd(o + 3, alpha * v.w);
}

// ---------------- bias + relu -------------------------------------------------
__global__ void bias_relu(float* __restrict__ p, const float* __restrict__ b,
                          int n, int stride) {
    int i = blockIdx.x * blockDim.x + threadIdx.x;
    if (i >= n) return;
    float v = p[i] + b[i % stride];
    p[i] = v > 0.f ? v : 0.f;
}

// ---------------- pooling -----------------------------------------------------
__global__ void pool_sum(const float* __restrict__ feat,
                         const int* __restrict__ batch,
                         float* __restrict__ pool) {
    int i = blockIdx.x * blockDim.x + threadIdx.x;
    if (i >= N_NODES * CDIM) return;
    int n = i / CDIM, c = i - n * CDIM;
    atomicAdd(&pool[batch[n] * CDIM + c], feat[i]);
}

__global__ void pool_cnt(const int* __restrict__ batch, float* __restrict__ cnt) {
    int n = blockIdx.x * blockDim.x + threadIdx.x;
    if (n >= N_NODES) return;
    atomicAdd(&cnt[batch[n]], 1.0f);
}

// ---------------- classifier --------------------------------------------------
__global__ void classifier(const float* __restrict__ pool, const float* __restrict__ cnt,
                           const float* __restrict__ Wc, const float* __restrict__ bc,
                           float* __restrict__ out) {
    int t = threadIdx.x;
    if (t >= NG * NOUT) return;
    int g = t / NOUT, o = t - g * NOUT;
    float inv = 1.0f / fmaxf(cnt[g], 1.0f);
    float sum = bc[o];
    for (int k = 0; k < CDIM; k++)
        sum = fmaf(pool[g * CDIM + k] * inv, Wc[k * NOUT + o], sum);
    out[t] = sum;
}

// ---------------- host orchestration ------------------------------------------
static inline int ceil_div(int a, int b) { return (a + b - 1) / b; }

extern "C" void kernel_launch(void* const* d_in, const int* in_sizes, int n_in,
                              void* d_out, int out_size) {
    const float* x      = (const float*)d_in[0];
    const int*   ei     = (const int*)d_in[1];
    const int*   batch  = (const int*)d_in[2];
    const float* W1     = (const float*)d_in[3];
    const float* asrc1  = (const float*)d_in[4];
    const float* adst1  = (const float*)d_in[5];
    const float* b1     = (const float*)d_in[6];
    const float* W2     = (const float*)d_in[7];
    const float* asrc2  = (const float*)d_in[8];
    const float* adst2  = (const float*)d_in[9];
    const float* b2     = (const float*)d_in[10];
    const float* Wc     = (const float*)d_in[11];
    const float* bc     = (const float*)d_in[12];
    float*       out    = (float*)d_out;

    float *zero, *minf, *h1, *als1, *ald1, *e1, *h2, *als2, *ald2, *e2;
    cudaGetSymbolAddress((void**)&zero, g_zero);
    cudaGetSymbolAddress((void**)&minf, g_minf);
    cudaGetSymbolAddress((void**)&h1,   g_h1);
    cudaGetSymbolAddress((void**)&als1, g_als1);
    cudaGetSymbolAddress((void**)&ald1, g_ald1);
    cudaGetSymbolAddress((void**)&e1,   g_e1);
    cudaGetSymbolAddress((void**)&h2,   g_h2);
    cudaGetSymbolAddress((void**)&als2, g_als2);
    cudaGetSymbolAddress((void**)&ald2, g_ald2);
    cudaGetSymbolAddress((void**)&e2,   g_e2);

    float* out1 = zero + Z_OUT1;
    float* den1 = zero + Z_DEN1;
    float* out2 = zero + Z_OUT2;
    float* den2 = zero + Z_DEN2;
    float* pool = zero + Z_POOL;
    float* cnt  = zero + Z_CNT;
    float* m1   = minf + MI_M1;
    float* m2   = minf + MI_M2;

    const int TB = 256;

    // --- init scratch (2 launches) ---
    fill4_kernel<<<ceil_div(ZTOT / 4, TB), TB>>>((float4*)zero, 0.f, ZTOT / 4);
    fill_kernel<<<ceil_div(MITOT, TB), TB>>>(minf, -INFINITY, MITOT);

    // --- layer 1 ---
    gemm_tf32<<<dim3(HC1 / 128, ceil_div(N_NODES, 128)), 256>>>(x, W1, h1, N_NODES, HC1, F_IN);
    att_logits<<<N_NODES, 32 * H1>>>(h1, asrc1, adst1, als1, ald1, H1);
    edge_logit_max<<<ceil_div(ETOT * H1, TB), TB>>>(ei, als1, ald1, e1, m1, H1);
    edge_exp_den<<<ceil_div(ETOT * H1, TB), TB>>>(ei, e1, m1, den1, H1);
    aggregate<<<ceil_div(ETOT * H1 * 32, TB), TB>>>(ei, h1, e1, den1, out1, H1);
    bias_relu<<<ceil_div(N_NODES * HC1, TB), TB>>>(out1, b1, N_NODES * HC1, HC1);

    // --- layer 2 ---
    gemm_tf32<<<dim3(CDIM / 128, ceil_div(N_NODES, 128)), 256>>>(out1, W2, h2, N_NODES, CDIM, HC1);
    att_logits<<<N_NODES, 32>>>(h2, asrc2, adst2, als2, ald2, 1);
    edge_logit_max<<<ceil_div(ETOT, TB), TB>>>(ei, als2, ald2, e2, m2, 1);
    edge_exp_den<<<ceil_div(ETOT, TB), TB>>>(ei, e2, m2, den2, 1);
    aggregate<<<ceil_div(ETOT * 32, TB), TB>>>(ei, h2, e2, den2, out2, 1);
    bias_relu<<<ceil_div(N_NODES * CDIM, TB), TB>>>(out2, b2, N_NODES * CDIM, CDIM);

    // --- pool + classify ---
    pool_sum<<<ceil_div(N_NODES * CDIM, TB), TB>>>(out2, batch, pool);
    pool_cnt<<<ceil_div(N_NODES, TB), TB>>>(batch, cnt);
    classifier<<<1, NG * NOUT>>>(pool, cnt, Wc, bc, out);
}

// round 4
// speedup vs baseline: 3.1337x; 1.8821x over previous
#include <cuda_runtime.h>
#include <math.h>

#define N_NODES 10000
#define N_EDGES 160000
#define ETOT (N_EDGES + N_NODES)   /* 170000 with self loops */
#define F_IN 768
#define H1 4
#define CDIM 128
#define HC1 (H1 * CDIM)            /* 512 */
#define NG 16
#define NOUT 10

// ---------------- scratch (device globals; no runtime allocation) -------------
// zeroed-per-call region
#define Z_DEG  0                       /* int degrees, as float-sized slots */
#define Z_POOL (Z_DEG + N_NODES)
#define Z_CNT  (Z_POOL + NG * CDIM)
#define ZTOT   (Z_CNT + NG)
__device__ float g_zero[ZTOT];

__device__ int   g_row_ptr[N_NODES + 1];
__device__ int   g_cursor [N_NODES];
__device__ int   g_csr_src[ETOT];

__device__ float g_h1  [N_NODES * HC1];
__device__ float g_out1[N_NODES * HC1];
__device__ float g_als1[N_NODES * H1];
__device__ float g_ald1[N_NODES * H1];

__device__ float g_h2  [N_NODES * CDIM];
__device__ float g_als2[N_NODES];
__device__ float g_ald2[N_NODES];

// ---------------- utility ------------------------------------------------------
__global__ void fill4_kernel(float4* p, float v, int n4) {
    int i = blockIdx.x * blockDim.x + threadIdx.x;
    if (i < n4) p[i] = make_float4(v, v, v, v);
}

// ---------------- CSR build ----------------------------------------------------
__global__ void hist_kernel(const int* __restrict__ ei, int* __restrict__ deg) {
    int idx = blockIdx.x * blockDim.x + threadIdx.x;
    if (idx >= ETOT) return;
    int d = (idx < N_EDGES) ? ei[N_EDGES + idx] : idx - N_EDGES;
    atomicAdd(&deg[d], 1);
}

__global__ __launch_bounds__(1024)
void scan_kernel(const int* __restrict__ deg, int* __restrict__ row_ptr,
                 int* __restrict__ cursor) {
    __shared__ int sm[1024];
    const int t = threadIdx.x;
    const int base = t * 10;
    int loc[10];
    int s = 0;
#pragma unroll
    for (int i = 0; i < 10; i++) {
        int idx = base + i;
        int v = (idx < N_NODES) ? deg[idx] : 0;
        loc[i] = s;
        s += v;
    }
    sm[t] = s;
    __syncthreads();
    for (int off = 1; off < 1024; off <<= 1) {
        int v = 0;
        if (t >= off) v = sm[t - off];
        __syncthreads();
        if (t >= off) sm[t] += v;
        __syncthreads();
    }
    int pre = (t > 0) ? sm[t - 1] : 0;
#pragma unroll
    for (int i = 0; i < 10; i++) {
        int idx = base + i;
        if (idx < N_NODES) {
            row_ptr[idx] = pre + loc[i];
            cursor[idx]  = pre + loc[i];
        }
    }
    if (t == 0) row_ptr[N_NODES] = ETOT;
}

__global__ void scatter_kernel(const int* __restrict__ ei, int* __restrict__ cursor,
                               int* __restrict__ csr_src) {
    int idx = blockIdx.x * blockDim.x + threadIdx.x;
    if (idx >= ETOT) return;
    int s, d;
    if (idx < N_EDGES) { s = ei[idx]; d = ei[N_EDGES + idx]; }
    else               { s = d = idx - N_EDGES; }
    int pos = atomicAdd(&cursor[d], 1);
    csr_src[pos] = s;
}

// ---------------- TF32 tensor-core GEMM ---------------------------------------
#define BK 16
#define A_PAD 20
#define B_PAD 136

__device__ __forceinline__ unsigned cvta_s(const void* p) {
    return (unsigned)__cvta_generic_to_shared(p);
}
__device__ __forceinline__ void cp_async16(unsigned s, const void* g) {
    asm volatile("cp.async.ca.shared.global [%0], [%1], 16;\n" :: "r"(s), "l"(g));
}
__device__ __forceinline__ void cp_commit() { asm volatile("cp.async.commit_group;\n"); }
__device__ __forceinline__ void cp_wait1() { asm volatile("cp.async.wait_group 1;\n"); }
__device__ __forceinline__ void cp_wait0() { asm volatile("cp.async.wait_group 0;\n"); }
__device__ __forceinline__ unsigned f2tf32(float f) {
    unsigned u;
    asm("cvt.rna.tf32.f32 %0, %1;\n" : "=r"(u) : "f"(f));
    return u;
}

__global__ __launch_bounds__(256)
void gemm_tf32(const float* __restrict__ A, const float* __restrict__ B,
               float* __restrict__ Cm, int M, int N, int K) {
    __shared__ float As[2][128 * A_PAD];
    __shared__ float Bs[2][BK * B_PAD];

    const int tid  = threadIdx.x;
    const int lane = tid & 31;
    const int warp = tid >> 5;
    const int wm = warp & 1;
    const int wn = warp >> 1;
    const int m_base = wm * 64;
    const int n_base = wn * 32;
    const int g = lane >> 2;
    const int t = lane & 3;
    const int row0 = blockIdx.y * 128;
    const int col0 = blockIdx.x * 128;

    float acc[4][4][4];
#pragma unroll
    for (int i = 0; i < 4; i++)
#pragma unroll
        for (int j = 0; j < 4; j++)
#pragma unroll
            for (int r = 0; r < 4; r++) acc[i][j][r] = 0.f;

    const int a_row0c = tid >> 2, a_c = (tid & 3);
    const int b_k0c   = tid >> 5, b_n = (tid & 31);
    const int KT = K / BK;

    auto load_tile = [&](int kt, int buf) {
        const int k0 = kt * BK;
#pragma unroll
        for (int h = 0; h < 2; h++) {
            int row = a_row0c + h * 64;
            int grow = row0 + row;
            if (grow >= M) grow = M - 1;
            unsigned s = cvta_s(&As[buf][row * A_PAD + a_c * 4]);
            cp_async16(s, &A[(size_t)grow * K + k0 + a_c * 4]);
        }
#pragma unroll
        for (int h = 0; h < 2; h++) {
            int k = b_k0c + h * 8;
            unsigned s = cvta_s(&Bs[buf][k * B_PAD + b_n * 4]);
            cp_async16(s, &B[(size_t)(k0 + k) * N + col0 + b_n * 4]);
        }
        cp_commit();
    };

    load_tile(0, 0);

    for (int kt = 0; kt < KT; kt++) {
        const int buf = kt & 1;
        if (kt + 1 < KT) { load_tile(kt + 1, buf ^ 1); cp_wait1(); }
        else             { cp_wait0(); }
        __syncthreads();

#pragma unroll
        for (int kk = 0; kk < 2; kk++) {
            const int ks = kk * 8;
            unsigned a[4][4];
#pragma unroll
            for (int mf = 0; mf < 4; mf++) {
                const int r = m_base + mf * 16;
                a[mf][0] = f2tf32(As[buf][(r + g)     * A_PAD + ks + t]);
                a[mf][1] = f2tf32(As[buf][(r + g + 8) * A_PAD + ks + t]);
                a[mf][2] = f2tf32(As[buf][(r + g)     * A_PAD + ks + t + 4]);
                a[mf][3] = f2tf32(As[buf][(r + g + 8) * A_PAD + ks + t + 4]);
            }
            unsigned b[4][2];
#pragma unroll
            for (int nf = 0; nf < 4; nf++) {
                const int c = n_base + nf * 8 + g;
                b[nf][0] = f2tf32(Bs[buf][(ks + t)     * B_PAD + c]);
                b[nf][1] = f2tf32(Bs[buf][(ks + t + 4) * B_PAD + c]);
            }
#pragma unroll
            for (int mf = 0; mf < 4; mf++)
#pragma unroll
                for (int nf = 0; nf < 4; nf++) {
                    asm volatile(
                        "mma.sync.aligned.m16n8k8.row.col.f32.tf32.tf32.f32 "
                        "{%0,%1,%2,%3}, {%4,%5,%6,%7}, {%8,%9}, {%0,%1,%2,%3};\n"
                        : "+f"(acc[mf][nf][0]), "+f"(acc[mf][nf][1]),
                          "+f"(acc[mf][nf][2]), "+f"(acc[mf][nf][3])
                        : "r"(a[mf][0]), "r"(a[mf][1]), "r"(a[mf][2]), "r"(a[mf][3]),
                          "r"(b[nf][0]), "r"(b[nf][1]));
                }
        }
        __syncthreads();
    }

#pragma unroll
    for (int mf = 0; mf < 4; mf++) {
        const int r0 = row0 + m_base + mf * 16 + g;
        const int r1 = r0 + 8;
#pragma unroll
        for (int nf = 0; nf < 4; nf++) {
            const int c = col0 + n_base + nf * 8 + t * 2;
            if (r0 < M)
                *(float2*)&Cm[(size_t)r0 * N + c] = make_float2(acc[mf][nf][0], acc[mf][nf][1]);
            if (r1 < M)
                *(float2*)&Cm[(size_t)r1 * N + c] = make_float2(acc[mf][nf][2], acc[mf][nf][3]);
        }
    }
}

// ---------------- attention logits: one warp per (node, head) ----------------
__global__ void att_logits(const float* __restrict__ feat,
                           const float* __restrict__ asrc,
                           const float* __restrict__ adst,
                           float* __restrict__ osrc, float* __restrict__ odst,
                           int H) {
    int n    = blockIdx.x;
    int h    = threadIdx.x >> 5;
    int lane = threadIdx.x & 31;
    const float* f = feat + ((size_t)n * H + h) * CDIM;
    float ss = 0.f, sd = 0.f;
#pragma unroll
    for (int c = lane; c < CDIM; c += 32) {
        float v = f[c];
        ss = fmaf(v, asrc[h * CDIM + c], ss);
        sd = fmaf(v, adst[h * CDIM + c], sd);
    }
#pragma unroll
    for (int o = 16; o; o >>= 1) {
        ss += __shfl_down_sync(0xffffffffu, ss, o);
        sd += __shfl_down_sync(0xffffffffu, sd, o);
    }
    if (lane == 0) { osrc[n * H + h] = ss; odst[n * H + h] = sd; }
}

// ---------------- fused softmax + aggregate (+bias/relu, opt pool) -----------
// warp per (dst node, head). No atomics on features (only pool when POOL).
template<int H, bool POOL>
__global__ __launch_bounds__(256)
void gat_fused(const int* __restrict__ row_ptr,
               const int* __restrict__ csr_src,
               const float* __restrict__ feat,     // [N, H*CDIM]
               const float* __restrict__ als,      // [N*H]
               const float* __restrict__ ald,      // [N*H]
               const float* __restrict__ bias,     // [H*CDIM]
               float* __restrict__ out,            // [N, H*CDIM] (if !POOL)
               const int* __restrict__ batch,      // (if POOL)
               float* __restrict__ pool) {         // [NG*CDIM] (if POOL)
    const int gw   = (blockIdx.x * blockDim.x + threadIdx.x) >> 5;
    const int lane = threadIdx.x & 31;
    const int n = gw / H, h = gw - n * H;
    if (n >= N_NODES) return;

    const int beg = row_ptr[n];
    const int end = row_ptr[n + 1];
    const float aldv = ald[n * H + h];

    // pass 1: max over edge logits (lanes over edges)
    float mx = -INFINITY;
    for (int i = beg + lane; i < end; i += 32) {
        int s = csr_src[i];
        float v = als[s * H + h] + aldv;
        v = v > 0.f ? v : 0.2f * v;
        mx = fmaxf(mx, v);
    }
#pragma unroll
    for (int o = 16; o; o >>= 1) mx = fmaxf(mx, __shfl_xor_sync(0xffffffffu, mx, o));

    // pass 2: denominator
    float den = 0.f;
    for (int i = beg + lane; i < end; i += 32) {
        int s = csr_src[i];
        float v = als[s * H + h] + aldv;
        v = v > 0.f ? v : 0.2f * v;
        den += __expf(v - mx);
    }
#pragma unroll
    for (int o = 16; o; o >>= 1) den += __shfl_xor_sync(0xffffffffu, den, o);
    const float inv = 1.0f / (den + 1e-16f);

    // pass 3: weighted gather (serial over edges, lanes over channels)
    float4 acc = make_float4(0.f, 0.f, 0.f, 0.f);
    for (int i = beg; i < end; i++) {
        int s = csr_src[i];                       // uniform across warp
        float v = als[s * H + h] + aldv;
        v = v > 0.f ? v : 0.2f * v;
        float alpha = __expf(v - mx) * inv;
        float4 f = ((const float4*)(feat + ((size_t)s * H + h) * CDIM))[lane];
        acc.x = fmaf(alpha, f.x, acc.x);
        acc.y = fmaf(alpha, f.y, acc.y);
        acc.z = fmaf(alpha, f.z, acc.z);
        acc.w = fmaf(alpha, f.w, acc.w);
    }
    float4 b4 = ((const float4*)(bias + h * CDIM))[lane];
    acc.x = fmaxf(acc.x + b4.x, 0.f);
    acc.y = fmaxf(acc.y + b4.y, 0.f);
    acc.z = fmaxf(acc.z + b4.z, 0.f);
    acc.w = fmaxf(acc.w + b4.w, 0.f);

    if (POOL) {
        float* p = pool + batch[n] * CDIM + lane * 4;
        atomicAdd(p + 0, acc.x);
        atomicAdd(p + 1, acc.y);
        atomicAdd(p + 2, acc.z);
        atomicAdd(p + 3, acc.w);
    } else {
        ((float4*)(out + ((size_t)n * H + h) * CDIM))[lane] = acc;
    }
}

// ---------------- count nodes per graph ---------------------------------------
__global__ void pool_cnt(const int* __restrict__ batch, float* __restrict__ cnt) {
    int n = blockIdx.x * blockDim.x + threadIdx.x;
    if (n >= N_NODES) return;
    atomicAdd(&cnt[batch[n]], 1.0f);
}

// ---------------- classifier ---------------------------------------------------
__global__ void classifier(const float* __restrict__ pool, const float* __restrict__ cnt,
                           const float* __restrict__ Wc, const float* __restrict__ bc,
                           float* __restrict__ out) {
    int t = threadIdx.x;
    if (t >= NG * NOUT) return;
    int g = t / NOUT, o = t - g * NOUT;
    float inv = 1.0f / fmaxf(cnt[g], 1.0f);
    float sum = bc[o];
    for (int k = 0; k < CDIM; k++)
        sum = fmaf(pool[g * CDIM + k] * inv, Wc[k * NOUT + o], sum);
    out[t] = sum;
}

// ---------------- host orchestration ------------------------------------------
static inline int ceil_div(int a, int b) { return (a + b - 1) / b; }

extern "C" void kernel_launch(void* const* d_in, const int* in_sizes, int n_in,
                              void* d_out, int out_size) {
    const float* x      = (const float*)d_in[0];
    const int*   ei     = (const int*)d_in[1];
    const int*   batch  = (const int*)d_in[2];
    const float* W1     = (const float*)d_in[3];
    const float* asrc1  = (const float*)d_in[4];
    const float* adst1  = (const float*)d_in[5];
    const float* b1     = (const float*)d_in[6];
    const float* W2     = (const float*)d_in[7];
    const float* asrc2  = (const float*)d_in[8];
    const float* adst2  = (const float*)d_in[9];
    const float* b2     = (const float*)d_in[10];
    const float* Wc     = (const float*)d_in[11];
    const float* bc     = (const float*)d_in[12];
    float*       out    = (float*)d_out;

    float *zero, *h1, *out1, *als1, *ald1, *h2, *als2, *ald2;
    int *row_ptr, *cursor, *csr_src;
    cudaGetSymbolAddress((void**)&zero,    g_zero);
    cudaGetSymbolAddress((void**)&row_ptr, g_row_ptr);
    cudaGetSymbolAddress((void**)&cursor,  g_cursor);
    cudaGetSymbolAddress((void**)&csr_src, g_csr_src);
    cudaGetSymbolAddress((void**)&h1,   g_h1);
    cudaGetSymbolAddress((void**)&out1, g_out1);
    cudaGetSymbolAddress((void**)&als1, g_als1);
    cudaGetSymbolAddress((void**)&ald1, g_ald1);
    cudaGetSymbolAddress((void**)&h2,   g_h2);
    cudaGetSymbolAddress((void**)&als2, g_als2);
    cudaGetSymbolAddress((void**)&ald2, g_ald2);

    int*   deg  = (int*)(zero + Z_DEG);
    float* pool = zero + Z_POOL;
    float* cnt  = zero + Z_CNT;

    const int TB = 256;

    // --- init + CSR build ---
    fill4_kernel<<<ceil_div(ZTOT / 4, TB), TB>>>((float4*)zero, 0.f, ZTOT / 4);
    hist_kernel<<<ceil_div(ETOT, TB), TB>>>(ei, deg);
    scan_kernel<<<1, 1024>>>(deg, row_ptr, cursor);
    scatter_kernel<<<ceil_div(ETOT, TB), TB>>>(ei, cursor, csr_src);

    // --- layer 1 ---
    gemm_tf32<<<dim3(HC1 / 128, ceil_div(N_NODES, 128)), 256>>>(x, W1, h1, N_NODES, HC1, F_IN);
    att_logits<<<N_NODES, 32 * H1>>>(h1, asrc1, adst1, als1, ald1, H1);
    gat_fused<H1, false><<<ceil_div(N_NODES * H1 * 32, TB), TB>>>(
        row_ptr, csr_src, h1, als1, ald1, b1, out1, nullptr, nullptr);

    // --- layer 2 (output fused straight into pool) ---
    gemm_tf32<<<dim3(CDIM / 128, ceil_div(N_NODES, 128)), 256>>>(out1, W2, h2, N_NODES, CDIM, HC1);
    att_logits<<<N_NODES, 32>>>(h2, asrc2, adst2, als2, ald2, 1);
    gat_fused<1, true><<<ceil_div(N_NODES * 32, TB), TB>>>(
        row_ptr, csr_src, h2, als2, ald2, b2, nullptr, batch, pool);

    // --- pool counts + classify ---
    pool_cnt<<<ceil_div(N_NODES, TB), TB>>>(batch, cnt);
    classifier<<<1, NG * NOUT>>>(pool, cnt, Wc, bc, out);
}